// round 1
// baseline (speedup 1.0000x reference)
#include <cuda_runtime.h>
#include <cstdint>

// Problem constants
#define E_    8
#define T_    2048
#define H_    2880
#define D_    2880
#define TWOD_ 5760

// Tiling
#define BM 128
#define BN 128
#define BK 32
#define ASTR 36    // BK + 4 pad -> conflict-free A frag reads
#define BSTR 136   // BN + 8 pad -> conflict-free B frag reads
#define AS_ELEMS (BM * ASTR)           // 4608
#define BS_ELEMS (BK * BSTR)           // 4352
#define SMEM_ELEMS (2 * (AS_ELEMS + BS_ELEMS))
#define SMEM_BYTES (SMEM_ELEMS * 4)    // 71680

// Scratch: hidden'[e][t][d] = rw[t,e] * glu_activation(...)  (188.7 MB)
__device__ float g_hidden[(size_t)E_ * T_ * D_];

__device__ __forceinline__ unsigned f2tf(float x) {
    unsigned r;
    asm("cvt.rna.tf32.f32 %0, %1;" : "=r"(r) : "f"(x));
    return r;
}

__device__ __forceinline__ void mma_tf32(float c[4], const unsigned a[4], const unsigned b[2]) {
    asm volatile(
        "mma.sync.aligned.m16n8k8.row.col.f32.tf32.tf32.f32 "
        "{%0,%1,%2,%3}, {%4,%5,%6,%7}, {%8,%9}, {%0,%1,%2,%3};\n"
        : "+f"(c[0]), "+f"(c[1]), "+f"(c[2]), "+f"(c[3])
        : "r"(a[0]), "r"(a[1]), "r"(a[2]), "r"(a[3]), "r"(b[0]), "r"(b[1]));
}

// Store staged registers (tf32-rounded) into one smem buffer pair.
__device__ __forceinline__ void stage_store(float* As, float* Bs,
                                            const float4* ar, const float4* br, int tid) {
#pragma unroll
    for (int it = 0; it < 4; it++) {
        int idx  = tid + it * 256;
        int rowa = idx >> 3, ca = (idx & 7) << 2;
        float* pa = As + rowa * ASTR + ca;
        pa[0] = __uint_as_float(f2tf(ar[it].x));
        pa[1] = __uint_as_float(f2tf(ar[it].y));
        pa[2] = __uint_as_float(f2tf(ar[it].z));
        pa[3] = __uint_as_float(f2tf(ar[it].w));
        int rowb = idx >> 5, cb = (idx & 31) << 2;
        float* pb = Bs + rowb * BSTR + cb;
        pb[0] = __uint_as_float(f2tf(br[it].x));
        pb[1] = __uint_as_float(f2tf(br[it].y));
        pb[2] = __uint_as_float(f2tf(br[it].z));
        pb[3] = __uint_as_float(f2tf(br[it].w));
    }
}

// One BK=32 slab of MMAs from a smem buffer pair.
__device__ __forceinline__ void compute_tile(const float* As, const float* Bs,
                                             float acc[2][8][4],
                                             int wm, int wn, int gid, int tig) {
#pragma unroll
    for (int kk = 0; kk < BK; kk += 8) {
        unsigned afr[2][4];
#pragma unroll
        for (int i = 0; i < 2; i++) {
            const float* p = As + (wm + i * 16 + gid) * ASTR + kk + tig;
            afr[i][0] = __float_as_uint(p[0]);
            afr[i][1] = __float_as_uint(p[8 * ASTR]);
            afr[i][2] = __float_as_uint(p[4]);
            afr[i][3] = __float_as_uint(p[8 * ASTR + 4]);
        }
        unsigned bfr[8][2];
#pragma unroll
        for (int j = 0; j < 8; j++) {
            const float* p = Bs + (kk + tig) * BSTR + wn + j * 8 + gid;
            bfr[j][0] = __float_as_uint(p[0]);
            bfr[j][1] = __float_as_uint(p[4 * BSTR]);
        }
#pragma unroll
        for (int i = 0; i < 2; i++)
#pragma unroll
            for (int j = 0; j < 8; j++)
                mma_tf32(acc[i][j], afr[i], bfr[j]);
    }
}

// ============================================================================
// GEMM1: gate_up = X @ W1[e] + b1[e]; fused GLU activation; scale by rw[t,e];
//        writes hidden' to g_hidden. All tile dims exact (no predication).
// ============================================================================
__global__ __launch_bounds__(256, 1)
void gemm1_kernel(const float* __restrict__ x, const float* __restrict__ w1,
                  const float* __restrict__ b1, const float* __restrict__ rw) {
    extern __shared__ float sm[];
    float* As0 = sm;
    float* As1 = sm + AS_ELEMS;
    float* Bs0 = sm + 2 * AS_ELEMS;
    float* Bs1 = sm + 2 * AS_ELEMS + BS_ELEMS;

    const int e  = blockIdx.z;
    const int n0 = blockIdx.x * BN;
    const int m0 = blockIdx.y * BM;
    const int tid  = threadIdx.x;
    const int lane = tid & 31;
    const int warp = tid >> 5;
    const int wm = (warp & 3) * 32;
    const int wn = (warp >> 2) * 64;
    const int gid = lane >> 2;
    const int tig = lane & 3;

    const float* Ag = x + (size_t)m0 * H_;
    const float* Bg = w1 + (size_t)e * H_ * TWOD_ + n0;

    float acc[2][8][4];
#pragma unroll
    for (int i = 0; i < 2; i++)
#pragma unroll
        for (int j = 0; j < 8; j++)
#pragma unroll
            for (int q = 0; q < 4; q++) acc[i][j][q] = 0.f;

    float4 ar[4], br[4];

    // prologue: stage tile 0
#pragma unroll
    for (int it = 0; it < 4; it++) {
        int idx  = tid + it * 256;
        int rowa = idx >> 3, ca = (idx & 7) << 2;
        ar[it] = *reinterpret_cast<const float4*>(Ag + (size_t)rowa * H_ + ca);
        int rowb = idx >> 5, cb = (idx & 31) << 2;
        br[it] = *reinterpret_cast<const float4*>(Bg + (size_t)rowb * TWOD_ + cb);
    }
    stage_store(As0, Bs0, ar, br, tid);
    __syncthreads();

    const int NKT = H_ / BK;  // 90
    int buf = 0;
    for (int kt = 0; kt < NKT; kt++) {
        if (kt + 1 < NKT) {
            const float* Ak = Ag + (kt + 1) * BK;
            const float* Bk = Bg + (size_t)(kt + 1) * BK * TWOD_;
#pragma unroll
            for (int it = 0; it < 4; it++) {
                int idx  = tid + it * 256;
                int rowa = idx >> 3, ca = (idx & 7) << 2;
                ar[it] = *reinterpret_cast<const float4*>(Ak + (size_t)rowa * H_ + ca);
                int rowb = idx >> 5, cb = (idx & 31) << 2;
                br[it] = *reinterpret_cast<const float4*>(Bk + (size_t)rowb * TWOD_ + cb);
            }
        }
        compute_tile(buf ? As1 : As0, buf ? Bs1 : Bs0, acc, wm, wn, gid, tig);
        if (kt + 1 < NKT) {
            stage_store(buf ? As0 : As1, buf ? Bs0 : Bs1, ar, br, tid);
            __syncthreads();
            buf ^= 1;
        }
    }

    // epilogue: bias + clamp + glu + routing-weight prescale -> g_hidden
    float rwv[2][2];
#pragma unroll
    for (int i = 0; i < 2; i++)
#pragma unroll
        for (int s = 0; s < 2; s++)
            rwv[i][s] = rw[(size_t)(m0 + wm + i * 16 + s * 8 + gid) * E_ + e];

    float* Hd = g_hidden + (size_t)e * T_ * D_;
#pragma unroll
    for (int i = 0; i < 2; i++) {
#pragma unroll
        for (int j = 0; j < 8; j++) {
            int col = n0 + wn + j * 8 + 2 * tig;  // even: gate at col, up at col+1
            float bg = b1[(size_t)e * TWOD_ + col];
            float bu = b1[(size_t)e * TWOD_ + col + 1];
#pragma unroll
            for (int s = 0; s < 2; s++) {
                float g = acc[i][j][2 * s]     + bg;
                float u = acc[i][j][2 * s + 1] + bu;
                g = fminf(g, 7.0f);
                u = fminf(fmaxf(u, -7.0f), 7.0f);
                float sig = 1.0f / (1.0f + __expf(-1.702f * g));
                float hv  = (u + 1.0f) * (g * sig);
                int row = m0 + wm + i * 16 + s * 8 + gid;
                Hd[(size_t)row * D_ + (col >> 1)] = rwv[i][s] * hv;
            }
        }
    }
}

// ============================================================================
// GEMM2: out[t,h] = sum_e hidden'[e,t,:] @ W2[e][:,h] + sum_e rw[t,e]*b2[e,h]
//        K stacked over experts (E*D = 23040). N tail predicated.
// ============================================================================
__global__ __launch_bounds__(256, 1)
void gemm2_kernel(const float* __restrict__ w2, const float* __restrict__ b2,
                  const float* __restrict__ rw, float* __restrict__ out) {
    extern __shared__ float sm[];
    float* As0 = sm;
    float* As1 = sm + AS_ELEMS;
    float* Bs0 = sm + 2 * AS_ELEMS;
    float* Bs1 = sm + 2 * AS_ELEMS + BS_ELEMS;

    const int n0 = blockIdx.x * BN;
    const int m0 = blockIdx.y * BM;
    const int tid  = threadIdx.x;
    const int lane = tid & 31;
    const int warp = tid >> 5;
    const int wm = (warp & 3) * 32;
    const int wn = (warp >> 2) * 64;
    const int gid = lane >> 2;
    const int tig = lane & 3;

    float acc[2][8][4];
#pragma unroll
    for (int i = 0; i < 2; i++)
#pragma unroll
        for (int j = 0; j < 8; j++)
#pragma unroll
            for (int q = 0; q < 4; q++) acc[i][j][q] = 0.f;

    float4 ar[4], br[4];

    const int KPE = D_ / BK;        // 90 k-tiles per expert
    const int NKT = E_ * KPE;       // 720

    // load for tile kt
    auto g2_load = [&](int kt) {
        int e   = kt / KPE;
        int kin = kt - e * KPE;
        const float* Ak = g_hidden + (size_t)e * T_ * D_ + (size_t)m0 * D_ + kin * BK;
        const float* Bk = w2 + (size_t)e * D_ * H_ + (size_t)(kin * BK) * H_;
#pragma unroll
        for (int it = 0; it < 4; it++) {
            int idx  = tid + it * 256;
            int rowa = idx >> 3, ca = (idx & 7) << 2;
            ar[it] = *reinterpret_cast<const float4*>(Ak + (size_t)rowa * D_ + ca);
            int rowb = idx >> 5, cb = (idx & 31) << 2;
            int col = n0 + cb;
            br[it] = (col < H_)
                         ? *reinterpret_cast<const float4*>(Bk + (size_t)rowb * H_ + col)
                         : make_float4(0.f, 0.f, 0.f, 0.f);
        }
    };

    g2_load(0);
    stage_store(As0, Bs0, ar, br, tid);
    __syncthreads();

    int buf = 0;
    for (int kt = 0; kt < NKT; kt++) {
        if (kt + 1 < NKT) g2_load(kt + 1);
        compute_tile(buf ? As1 : As0, buf ? Bs1 : Bs0, acc, wm, wn, gid, tig);
        if (kt + 1 < NKT) {
            stage_store(buf ? As0 : As1, buf ? Bs0 : Bs1, ar, br, tid);
            __syncthreads();
            buf ^= 1;
        }
    }

    // epilogue: add sum_e rw[t,e]*b2[e,h], write out (predicated on col<H)
    float rwr[2][2][E_];
#pragma unroll
    for (int i = 0; i < 2; i++)
#pragma unroll
        for (int s = 0; s < 2; s++) {
            int row = m0 + wm + i * 16 + s * 8 + gid;
#pragma unroll
            for (int ee = 0; ee < E_; ee++)
                rwr[i][s][ee] = rw[(size_t)row * E_ + ee];
        }

#pragma unroll
    for (int i = 0; i < 2; i++) {
#pragma unroll
        for (int j = 0; j < 8; j++) {
            int col = n0 + wn + j * 8 + 2 * tig;
            if (col < H_) {
#pragma unroll
                for (int s = 0; s < 2; s++) {
                    int row = m0 + wm + i * 16 + s * 8 + gid;
                    float bs0 = 0.f, bs1 = 0.f;
#pragma unroll
                    for (int ee = 0; ee < E_; ee++) {
                        float r = rwr[i][s][ee];
                        bs0 += r * b2[(size_t)ee * H_ + col];
                        bs1 += r * b2[(size_t)ee * H_ + col + 1];
                    }
                    out[(size_t)row * H_ + col]     = acc[i][j][2 * s]     + bs0;
                    out[(size_t)row * H_ + col + 1] = acc[i][j][2 * s + 1] + bs1;
                }
            }
        }
    }
}

extern "C" void kernel_launch(void* const* d_in, const int* in_sizes, int n_in,
                              void* d_out, int out_size) {
    (void)in_sizes; (void)n_in; (void)out_size;
    const float* x  = (const float*)d_in[0];  // hidden_states [2,1024,2880]
    const float* rw = (const float*)d_in[1];  // routing_weights [2048,8]
    const float* w1 = (const float*)d_in[2];  // gate_up_proj [8,2880,5760]
    const float* b1 = (const float*)d_in[3];  // gate_up_proj_bias [8,5760]
    const float* w2 = (const float*)d_in[4];  // down_proj [8,2880,2880]
    const float* b2 = (const float*)d_in[5];  // down_proj_bias [8,2880]
    float* out = (float*)d_out;               // [2,1024,2880] f32

    cudaFuncSetAttribute(gemm1_kernel, cudaFuncAttributeMaxDynamicSharedMemorySize, SMEM_BYTES);
    cudaFuncSetAttribute(gemm2_kernel, cudaFuncAttributeMaxDynamicSharedMemorySize, SMEM_BYTES);

    gemm1_kernel<<<dim3(TWOD_ / BN, T_ / BM, E_), 256, SMEM_BYTES>>>(x, w1, b1, rw);
    gemm2_kernel<<<dim3((H_ + BN - 1) / BN, T_ / BM, 1), 256, SMEM_BYTES>>>(w2, b2, rw, out);
}